// round 12
// baseline (speedup 1.0000x reference)
#include <cuda_runtime.h>

#define NE_MAX 500000
#define NRELS 256
#define DIM 256
#define NKEYS 4096        // 13 node-buckets (node>>14) x 256 rels = 3328 used
#define RCHUNK 512        // items per block in reduce

typedef unsigned int u32;

// ---- scratch (device globals; no allocation allowed) ----
__device__ int   g_counts[NRELS];           // edges per rel (for the mean)
__device__ int   g_kcounts[NKEYS];          // items per (bucket,rel) key
__device__ int   g_kcursor[NKEYS];          // exclusive prefix / scatter cursor
__device__ u32   g_items[2 * NE_MAX];       // node(18) | rel(8)<<18 | which(1)<<26
__device__ float g_Asum[2 * NRELS * DIM];   // rows 0-255 src sums, 256-511 dst sums
// A: rows 0-255 src_avg, 256-511 dst_avg, 512-767 h_src, 768-1023 h_dst
__device__ float g_A[1024 * DIM];
// G: [1024][768] = A @ Wsel^T  (rows <512 use W_ih, rows >=512 use W_hh)
__device__ float g_G[1024 * 768];

// ---------------- phase 0: zero counters + partial-sum buffer ----------------
__global__ void init_kernel() {
    int id = blockIdx.x * blockDim.x + threadIdx.x;   // 32768
    if (id < NRELS)  g_counts[id] = 0;
    if (id < NKEYS)  g_kcounts[id] = 0;
    ((float4*)g_Asum)[id] = make_float4(0.f, 0.f, 0.f, 0.f);
}

// ------- phase 1: histogram of (bucket,rel) keys + rel counts + h unpack -----
__global__ void hist_kernel(const int* __restrict__ src,
                            const int* __restrict__ dst,
                            const int* __restrict__ rel, int n,
                            const float* __restrict__ dyn) {
    __shared__ int h[NKEYS];
    __shared__ int hr[NRELS];
    int t = threadIdx.x;
    for (int i = t; i < NKEYS; i += 256) h[i] = 0;
    hr[t] = 0;
    __syncthreads();
    int gid = blockIdx.x * blockDim.x + t;
    for (int i = gid; i < n; i += gridDim.x * blockDim.x) {
        int r = rel[i];
        int s = src[i];
        int d = dst[i];
        atomicAdd(&h[((u32)s >> 14) * NRELS + r], 1);
        atomicAdd(&h[((u32)d >> 14) * NRELS + r], 1);
        atomicAdd(&hr[r], 1);
    }
    // independent: unpack dyn [r][0][d][k] -> g_A rows 512 + k*256 + r
    if (gid < 2 * NRELS * DIM) {           // 512*256 = 131072 = grid size exactly
        int r = gid >> 9;
        int rem = gid & 511;
        int d = rem >> 1;
        int k = rem & 1;
        g_A[(512 + k * NRELS + r) * DIM + d] = dyn[r * (DIM * 2) + d * 2 + k];
    }
    __syncthreads();
    for (int i = t; i < NKEYS; i += 256) {
        int v = h[i];
        if (v) atomicAdd(&g_kcounts[i], v);
    }
    int v = hr[t];
    if (v) atomicAdd(&g_counts[t], v);
}

// ---------------- phase 2: exclusive scan over 4096 keys (1 block, 1024 thr) --
__global__ void scan_keys_kernel() {
    __shared__ int part[1024];
    int t = threadIdx.x;
    int v0 = g_kcounts[4 * t + 0];
    int v1 = g_kcounts[4 * t + 1];
    int v2 = g_kcounts[4 * t + 2];
    int v3 = g_kcounts[4 * t + 3];
    int local = v0 + v1 + v2 + v3;
    part[t] = local;
    __syncthreads();
    for (int off = 1; off < 1024; off <<= 1) {
        int x = (t >= off) ? part[t - off] : 0;
        __syncthreads();
        part[t] += x;
        __syncthreads();
    }
    int excl = part[t] - local;
    g_kcursor[4 * t + 0] = excl;
    g_kcursor[4 * t + 1] = excl + v0;
    g_kcursor[4 * t + 2] = excl + v0 + v1;
    g_kcursor[4 * t + 3] = excl + v0 + v1 + v2;
}

// ------- phase 3: scatter items (direct global-cursor atomics, spread) -------
__global__ void __launch_bounds__(256) scatter_items_kernel(const int* __restrict__ src,
                                                            const int* __restrict__ dst,
                                                            const int* __restrict__ rel, int n) {
    int gid = blockIdx.x * blockDim.x + threadIdx.x;
    for (int i = gid; i < n; i += gridDim.x * blockDim.x) {
        u32 s = (u32)src[i], d = (u32)dst[i], r = (u32)rel[i];
        int ks = (int)((s >> 14) * NRELS + r);
        int kd = (int)((d >> 14) * NRELS + r);
        int ps = atomicAdd(&g_kcursor[ks], 1);
        g_items[ps] = s | (r << 18);
        int pd = atomicAdd(&g_kcursor[kd], 1);
        g_items[pd] = d | (r << 18) | (1u << 26);
    }
}

// ---------------- phase 4: bucket-local segment-sum over sorted items ---------
__device__ __forceinline__ void flush_accum(int rel_id, int q,
                                            const float4& as, const float4& ad) {
    float* ps = &g_Asum[rel_id * DIM + q];
    float* pd = &g_Asum[(NRELS + rel_id) * DIM + q];
    atomicAdd(ps + 0, as.x); atomicAdd(ps + 1, as.y);
    atomicAdd(ps + 2, as.z); atomicAdd(ps + 3, as.w);
    atomicAdd(pd + 0, ad.x); atomicAdd(pd + 1, ad.y);
    atomicAdd(pd + 2, ad.z); atomicAdd(pd + 3, ad.w);
}

__device__ __forceinline__ void accum_item(u32 p, const float4& v, int q,
                                           int& cur, float4& as, float4& ad) {
    int r = (int)((p >> 18) & 0xFF);
    if (r != cur) {
        if (cur >= 0) flush_accum(cur, q, as, ad);
        as = make_float4(0.f, 0.f, 0.f, 0.f);
        ad = as;
        cur = r;
    }
    if (p & (1u << 26)) {
        ad.x += v.x; ad.y += v.y; ad.z += v.z; ad.w += v.w;
    } else {
        as.x += v.x; as.y += v.y; as.z += v.z; as.w += v.w;
    }
}

__global__ void __launch_bounds__(256) reduce_kernel(const float* __restrict__ emb, int m) {
    int beg = blockIdx.x * RCHUNK;
    int end = min(m, beg + RCHUNK);
    int t = threadIdx.x;
    int sub = t >> 6;            // 4 item streams per block, stride 4
    int q   = (t & 63) << 2;     // float4 column

    float4 as = make_float4(0.f, 0.f, 0.f, 0.f);
    float4 ad = as;
    int cur = -1;

    int i = beg + sub;
    // main loop: 4 items per iteration -> 4 independent float4 gathers in flight
    for (; i + 12 < end; i += 16) {
        u32 p0 = __ldg(&g_items[i]);
        u32 p1 = __ldg(&g_items[i + 4]);
        u32 p2 = __ldg(&g_items[i + 8]);
        u32 p3 = __ldg(&g_items[i + 12]);
        float4 v0 = __ldg((const float4*)&emb[(p0 & 0x3FFFF) * DIM + q]);
        float4 v1 = __ldg((const float4*)&emb[(p1 & 0x3FFFF) * DIM + q]);
        float4 v2 = __ldg((const float4*)&emb[(p2 & 0x3FFFF) * DIM + q]);
        float4 v3 = __ldg((const float4*)&emb[(p3 & 0x3FFFF) * DIM + q]);
        accum_item(p0, v0, q, cur, as, ad);
        accum_item(p1, v1, q, cur, as, ad);
        accum_item(p2, v2, q, cur, as, ad);
        accum_item(p3, v3, q, cur, as, ad);
    }
    // tail
    for (; i < end; i += 4) {
        u32 p = __ldg(&g_items[i]);
        float4 v = __ldg((const float4*)&emb[(p & 0x3FFFF) * DIM + q]);
        accum_item(p, v, q, cur, as, ad);
    }
    if (cur >= 0) flush_accum(cur, q, as, ad);
}

// ---------------- phase 4b: divide by counts ----------------
__global__ void finalize_kernel() {
    int r = blockIdx.x, t = threadIdx.x;
    int c = g_counts[r];
    float inv = 1.f / (float)(c > 0 ? c : 1);
    g_A[r * DIM + t]           = g_Asum[r * DIM + t] * inv;
    g_A[(NRELS + r) * DIM + t] = g_Asum[(NRELS + r) * DIM + t] * inv;
}

// ---------------- phase 5: GEMM  G[1024][768] = A[1024][256] @ Wsel[768][256]^T
#define TM 64
#define TN 64
#define TK 16
__global__ void __launch_bounds__(256) gemm_kernel(const float* __restrict__ Wih,
                                                   const float* __restrict__ Whh) {
    __shared__ float As[TK][TM + 4];
    __shared__ float Bs[TK][TN + 4];
    int bm = blockIdx.y, bn = blockIdx.x;
    const float* Wsel = (bm < 8) ? Wih : Whh;

    int tid = threadIdx.x;
    int tx = tid & 15;
    int ty = tid >> 4;
    int lrow  = tid >> 2;
    int lcol4 = (tid & 3) * 4;

    const float* Aptr = g_A  + (bm * TM + lrow) * 256 + lcol4;
    const float* Bptr = Wsel + (bn * TN + lrow) * 256 + lcol4;

    float c[4][4] = {};

    for (int k0 = 0; k0 < 256; k0 += TK) {
        float4 a4 = *(const float4*)(Aptr + k0);
        float4 b4 = *(const float4*)(Bptr + k0);
        As[lcol4 + 0][lrow] = a4.x;
        As[lcol4 + 1][lrow] = a4.y;
        As[lcol4 + 2][lrow] = a4.z;
        As[lcol4 + 3][lrow] = a4.w;
        Bs[lcol4 + 0][lrow] = b4.x;
        Bs[lcol4 + 1][lrow] = b4.y;
        Bs[lcol4 + 2][lrow] = b4.z;
        Bs[lcol4 + 3][lrow] = b4.w;
        __syncthreads();
#pragma unroll
        for (int kk = 0; kk < TK; kk++) {
            float4 av = *(const float4*)&As[kk][ty * 4];
            float4 bv = *(const float4*)&Bs[kk][tx * 4];
            c[0][0] += av.x * bv.x; c[0][1] += av.x * bv.y; c[0][2] += av.x * bv.z; c[0][3] += av.x * bv.w;
            c[1][0] += av.y * bv.x; c[1][1] += av.y * bv.y; c[1][2] += av.y * bv.z; c[1][3] += av.y * bv.w;
            c[2][0] += av.z * bv.x; c[2][1] += av.z * bv.y; c[2][2] += av.z * bv.z; c[2][3] += av.z * bv.w;
            c[3][0] += av.w * bv.x; c[3][1] += av.w * bv.y; c[3][2] += av.w * bv.z; c[3][3] += av.w * bv.w;
        }
        __syncthreads();
    }

#pragma unroll
    for (int i = 0; i < 4; i++) {
        int row = bm * TM + ty * 4 + i;
        int col = bn * TN + tx * 4;
        float4 v = make_float4(c[i][0], c[i][1], c[i][2], c[i][3]);
        *(float4*)&g_G[row * 768 + col] = v;
    }
}

// ---------------- phase 6: GRU gates + output ----------------
__global__ void gate_kernel(const float* __restrict__ bih,
                            const float* __restrict__ bhh,
                            float* __restrict__ out) {
    int r = blockIdx.x;
    int d = threadIdx.x;

    float bir = bih[d], biz = bih[256 + d], bin_ = bih[512 + d];
    float bhr = bhh[d], bhz = bhh[256 + d], bhn = bhh[512 + d];

#pragma unroll
    for (int k = 0; k < 2; k++) {   // 0 = src, 1 = dst
        int xrow = k * 256 + r;
        int hrow = 512 + k * 256 + r;
        float ir  = g_G[xrow * 768 + d]       + bir;
        float iz  = g_G[xrow * 768 + 256 + d] + biz;
        float in_ = g_G[xrow * 768 + 512 + d] + bin_;
        float hr  = g_G[hrow * 768 + d]       + bhr;
        float hz  = g_G[hrow * 768 + 256 + d] + bhz;
        float hn  = g_G[hrow * 768 + 512 + d] + bhn;
        float h   = g_A[hrow * DIM + d];

        float rg = 1.f / (1.f + expf(-(ir + hr)));
        float z  = 1.f / (1.f + expf(-(iz + hz)));
        float nv = tanhf(in_ + rg * hn);
        out[r * (DIM * 2) + d * 2 + k] = (1.f - z) * nv + z * h;
    }
}

extern "C" void kernel_launch(void* const* d_in, const int* in_sizes, int n_in,
                              void* d_out, int out_size) {
    const int*   src = (const int*)d_in[0];
    const int*   dst = (const int*)d_in[1];
    const int*   rel = (const int*)d_in[2];
    const float* emb = (const float*)d_in[3];
    const float* dyn = (const float*)d_in[4];
    const float* Wih = (const float*)d_in[5];
    const float* Whh = (const float*)d_in[6];
    const float* bih = (const float*)d_in[7];
    const float* bhh = (const float*)d_in[8];
    float* out = (float*)d_out;
    int n = in_sizes[0];
    int m = 2 * n;   // items

    init_kernel<<<128, 256>>>();
    hist_kernel<<<512, 256>>>(src, dst, rel, n, dyn);
    scan_keys_kernel<<<1, 1024>>>();
    scatter_items_kernel<<<977, 256>>>(src, dst, rel, n);
    int nbR = (m + RCHUNK - 1) / RCHUNK;
    reduce_kernel<<<nbR, 256>>>(emb, m);
    finalize_kernel<<<256, 256>>>();
    gemm_kernel<<<dim3(12, 16), 256>>>(Wih, Whh);
    gate_kernel<<<256, 256>>>(bih, bhh, out);
}

// round 13
// speedup vs baseline: 1.2706x; 1.2706x over previous
#include <cuda_runtime.h>

#define NE_MAX 500000
#define NRELS 256
#define DIM 256
#define NBUCKETS 13            // node >> 14 for N_NODES=200000
#define NKEYS (NBUCKETS * NRELS)   // 3328 bins
#define SLAB_CAP 2048          // items per bin (avg ~300; huge safety margin)

typedef unsigned int u32;

// ---- scratch (device globals; no allocation allowed) ----
__device__ int   g_bincnt[NKEYS];                   // items per (bucket,rel)
__device__ u32   g_slab[NKEYS * SLAB_CAP];          // node(18) | which(1)<<18
__device__ float g_AsumB[NBUCKETS][2 * NRELS * DIM]; // per-bucket partial sums (6.8MB)
// A: rows 0-255 src_avg, 256-511 dst_avg, 512-767 h_src, 768-1023 h_dst
__device__ float g_A[1024 * DIM];
// G: [1024][768] = A @ Wsel^T  (rows <512 use W_ih, rows >=512 use W_hh)
__device__ float g_G[1024 * 768];

// ---------------- phase 0: zero bin counters ----------------
__global__ void init_kernel() {
    int id = blockIdx.x * blockDim.x + threadIdx.x;   // 4096
    if (id < NKEYS) g_bincnt[id] = 0;
}

// ------- phase 1: scatter items into per-bin slabs (bump allocation) -------
// 4 edges per thread -> 8 independent atomic+store chains in flight.
__global__ void __launch_bounds__(256) scatter_kernel(const int* __restrict__ src,
                                                      const int* __restrict__ dst,
                                                      const int* __restrict__ rel, int n) {
    int beg = blockIdx.x * (256 * 4) + threadIdx.x;
    int s[4], d[4], r[4];
    bool ok[4];
#pragma unroll
    for (int j = 0; j < 4; j++) {
        int i = beg + j * 256;           // coalesced
        ok[j] = (i < n);
        if (ok[j]) { s[j] = src[i]; d[j] = dst[i]; r[j] = rel[i]; }
    }
    int ps[4], pd[4];
#pragma unroll
    for (int j = 0; j < 4; j++) {        // 8 independent atomics back-to-back
        if (ok[j]) {
            int ks = (int)(((u32)s[j] >> 14) * NRELS + (u32)r[j]);
            int kd = (int)(((u32)d[j] >> 14) * NRELS + (u32)r[j]);
            ps[j] = atomicAdd(&g_bincnt[ks], 1) + ks * SLAB_CAP;
            pd[j] = atomicAdd(&g_bincnt[kd], 1) + kd * SLAB_CAP;
        }
    }
#pragma unroll
    for (int j = 0; j < 4; j++) {
        if (ok[j]) {
            if ((ps[j] & (SLAB_CAP - 1)) < SLAB_CAP) g_slab[ps[j]] = (u32)s[j];
            if ((pd[j] & (SLAB_CAP - 1)) < SLAB_CAP) g_slab[pd[j]] = (u32)d[j] | (1u << 18);
        }
    }
}

// ------- phase 2: one block per bin; accumulate, combine, plain store -------
__global__ void __launch_bounds__(256) reduce_kernel(const float* __restrict__ emb) {
    int key    = blockIdx.x;            // 0..NKEYS-1
    int bucket = key >> 8;              // key / NRELS
    int rel    = key & 255;
    int cnt    = min(g_bincnt[key], SLAB_CAP);

    int t = threadIdx.x;
    int sub = t >> 6;                   // 4 item streams
    int l   = t & 63;
    int q   = l << 2;                   // float4 column

    const u32* bin = g_slab + (size_t)key * SLAB_CAP;

    float4 as = make_float4(0.f, 0.f, 0.f, 0.f);
    float4 ad = as;

    int i = sub;
    // 2 items in flight per stream (8 gathers per 256-thread block iteration)
    for (; i + 4 < cnt; i += 8) {
        u32 p0 = bin[i];                // uniform per stream (broadcast load)
        u32 p1 = bin[i + 4];
        float4 v0 = __ldg((const float4*)&emb[(p0 & 0x3FFFF) * DIM + q]);
        float4 v1 = __ldg((const float4*)&emb[(p1 & 0x3FFFF) * DIM + q]);
        if (p0 >> 18) { ad.x += v0.x; ad.y += v0.y; ad.z += v0.z; ad.w += v0.w; }
        else          { as.x += v0.x; as.y += v0.y; as.z += v0.z; as.w += v0.w; }
        if (p1 >> 18) { ad.x += v1.x; ad.y += v1.y; ad.z += v1.z; ad.w += v1.w; }
        else          { as.x += v1.x; as.y += v1.y; as.z += v1.z; as.w += v1.w; }
    }
    for (; i < cnt; i += 4) {
        u32 p = bin[i];
        float4 v = __ldg((const float4*)&emb[(p & 0x3FFFF) * DIM + q]);
        if (p >> 18) { ad.x += v.x; ad.y += v.y; ad.z += v.z; ad.w += v.w; }
        else         { as.x += v.x; as.y += v.y; as.z += v.z; as.w += v.w; }
    }

    // combine 4 streams in smem, then exclusive-owner plain store
    __shared__ float4 s_s[4][64];
    __shared__ float4 s_d[4][64];
    s_s[sub][l] = as;
    s_d[sub][l] = ad;
    __syncthreads();
    if (sub == 0) {
        float4 a = s_s[0][l], b = s_s[1][l], c = s_s[2][l], e = s_s[3][l];
        a.x += b.x + c.x + e.x; a.y += b.y + c.y + e.y;
        a.z += b.z + c.z + e.z; a.w += b.w + c.w + e.w;
        float4 f = s_d[0][l], g = s_d[1][l], h = s_d[2][l], k = s_d[3][l];
        f.x += g.x + h.x + k.x; f.y += g.y + h.y + k.y;
        f.z += g.z + h.z + k.z; f.w += g.w + h.w + k.w;
        *(float4*)&g_AsumB[bucket][rel * DIM + q]           = a;
        *(float4*)&g_AsumB[bucket][(NRELS + rel) * DIM + q] = f;
    }
}

// ------- phase 3: sum buckets, divide by counts, unpack hidden state -------
__global__ void finalize_kernel(const float* __restrict__ dyn) {
    int r = blockIdx.x, t = threadIdx.x;
    float s = 0.f, d = 0.f;
    int items = 0;
#pragma unroll
    for (int b = 0; b < NBUCKETS; b++) {
        items += g_bincnt[(b << 8) + r];
        s += g_AsumB[b][r * DIM + t];
        d += g_AsumB[b][(NRELS + r) * DIM + t];
    }
    int cnt = items >> 1;                      // src+dst items per edge
    float inv = 1.f / (float)(cnt > 0 ? cnt : 1);
    g_A[r * DIM + t]           = s * inv;
    g_A[(NRELS + r) * DIM + t] = d * inv;
    // unpack dyn [r][0][d][k] -> h rows
    g_A[(512 + r) * DIM + t] = dyn[r * (DIM * 2) + t * 2 + 0];
    g_A[(768 + r) * DIM + t] = dyn[r * (DIM * 2) + t * 2 + 1];
}

// ---------------- phase 4: GEMM  G[1024][768] = A[1024][256] @ Wsel[768][256]^T
#define TM 64
#define TN 64
#define TK 16
__global__ void __launch_bounds__(256) gemm_kernel(const float* __restrict__ Wih,
                                                   const float* __restrict__ Whh) {
    __shared__ float As[TK][TM + 4];
    __shared__ float Bs[TK][TN + 4];
    int bm = blockIdx.y, bn = blockIdx.x;
    const float* Wsel = (bm < 8) ? Wih : Whh;

    int tid = threadIdx.x;
    int tx = tid & 15;
    int ty = tid >> 4;
    int lrow  = tid >> 2;
    int lcol4 = (tid & 3) * 4;

    const float* Aptr = g_A  + (bm * TM + lrow) * 256 + lcol4;
    const float* Bptr = Wsel + (bn * TN + lrow) * 256 + lcol4;

    float c[4][4] = {};

    for (int k0 = 0; k0 < 256; k0 += TK) {
        float4 a4 = *(const float4*)(Aptr + k0);
        float4 b4 = *(const float4*)(Bptr + k0);
        As[lcol4 + 0][lrow] = a4.x;
        As[lcol4 + 1][lrow] = a4.y;
        As[lcol4 + 2][lrow] = a4.z;
        As[lcol4 + 3][lrow] = a4.w;
        Bs[lcol4 + 0][lrow] = b4.x;
        Bs[lcol4 + 1][lrow] = b4.y;
        Bs[lcol4 + 2][lrow] = b4.z;
        Bs[lcol4 + 3][lrow] = b4.w;
        __syncthreads();
#pragma unroll
        for (int kk = 0; kk < TK; kk++) {
            float4 av = *(const float4*)&As[kk][ty * 4];
            float4 bv = *(const float4*)&Bs[kk][tx * 4];
            c[0][0] += av.x * bv.x; c[0][1] += av.x * bv.y; c[0][2] += av.x * bv.z; c[0][3] += av.x * bv.w;
            c[1][0] += av.y * bv.x; c[1][1] += av.y * bv.y; c[1][2] += av.y * bv.z; c[1][3] += av.y * bv.w;
            c[2][0] += av.z * bv.x; c[2][1] += av.z * bv.y; c[2][2] += av.z * bv.z; c[2][3] += av.z * bv.w;
            c[3][0] += av.w * bv.x; c[3][1] += av.w * bv.y; c[3][2] += av.w * bv.z; c[3][3] += av.w * bv.w;
        }
        __syncthreads();
    }

#pragma unroll
    for (int i = 0; i < 4; i++) {
        int row = bm * TM + ty * 4 + i;
        int col = bn * TN + tx * 4;
        float4 v = make_float4(c[i][0], c[i][1], c[i][2], c[i][3]);
        *(float4*)&g_G[row * 768 + col] = v;
    }
}

// ---------------- phase 5: GRU gates + output ----------------
__global__ void gate_kernel(const float* __restrict__ bih,
                            const float* __restrict__ bhh,
                            float* __restrict__ out) {
    int r = blockIdx.x;
    int d = threadIdx.x;

    float bir = bih[d], biz = bih[256 + d], bin_ = bih[512 + d];
    float bhr = bhh[d], bhz = bhh[256 + d], bhn = bhh[512 + d];

#pragma unroll
    for (int k = 0; k < 2; k++) {   // 0 = src, 1 = dst
        int xrow = k * 256 + r;
        int hrow = 512 + k * 256 + r;
        float ir  = g_G[xrow * 768 + d]       + bir;
        float iz  = g_G[xrow * 768 + 256 + d] + biz;
        float in_ = g_G[xrow * 768 + 512 + d] + bin_;
        float hr  = g_G[hrow * 768 + d]       + bhr;
        float hz  = g_G[hrow * 768 + 256 + d] + bhz;
        float hn  = g_G[hrow * 768 + 512 + d] + bhn;
        float h   = g_A[hrow * DIM + d];

        float rg = 1.f / (1.f + expf(-(ir + hr)));
        float z  = 1.f / (1.f + expf(-(iz + hz)));
        float nv = tanhf(in_ + rg * hn);
        out[r * (DIM * 2) + d * 2 + k] = (1.f - z) * nv + z * h;
    }
}

extern "C" void kernel_launch(void* const* d_in, const int* in_sizes, int n_in,
                              void* d_out, int out_size) {
    const int*   src = (const int*)d_in[0];
    const int*   dst = (const int*)d_in[1];
    const int*   rel = (const int*)d_in[2];
    const float* emb = (const float*)d_in[3];
    const float* dyn = (const float*)d_in[4];
    const float* Wih = (const float*)d_in[5];
    const float* Whh = (const float*)d_in[6];
    const float* bih = (const float*)d_in[7];
    const float* bhh = (const float*)d_in[8];
    float* out = (float*)d_out;
    int n = in_sizes[0];

    init_kernel<<<16, 256>>>();
    int nbS = (n + 1024 - 1) / 1024;
    scatter_kernel<<<nbS, 256>>>(src, dst, rel, n);
    reduce_kernel<<<NKEYS, 256>>>(emb);
    finalize_kernel<<<256, 256>>>(dyn);
    gemm_kernel<<<dim3(12, 16), 256>>>(Wih, Whh);
    gate_kernel<<<256, 256>>>(bih, bhh, out);
}

// round 14
// speedup vs baseline: 1.2863x; 1.0123x over previous
#include <cuda_runtime.h>

#define NE_MAX 500000
#define NRELS 256
#define DIM 256
#define NBUCKETS 13            // node >> 14 for N_NODES=200000
#define NKEYS (NBUCKETS * NRELS)   // 3328 bins
#define SLAB_CAP 2048          // items per bin (avg ~300; huge safety margin)

typedef unsigned int u32;

// ---- scratch (device globals; zero at module load) ----
// Invariant: g_bincnt == 0 at entry of every kernel_launch call.
// finalize_kernel restores it after consuming the counts.
__device__ int   g_bincnt[NKEYS];                   // items per (bucket,rel)
__device__ u32   g_slab[NKEYS * SLAB_CAP];          // node(18) | which(1)<<18
__device__ float g_AsumB[NBUCKETS][2 * NRELS * DIM]; // per-bucket partial sums (6.8MB)
// A: rows 0-255 src_avg, 256-511 dst_avg, 512-767 h_src, 768-1023 h_dst
__device__ float g_A[1024 * DIM];
// G: [1024][768] = A @ Wsel^T  (rows <512 use W_ih, rows >=512 use W_hh)
__device__ float g_G[1024 * 768];

// ------- phase 1: scatter items into per-bin slabs (bump allocation) -------
// 4 edges per thread -> 8 independent atomic+store chains in flight.
__global__ void __launch_bounds__(256) scatter_kernel(const int* __restrict__ src,
                                                      const int* __restrict__ dst,
                                                      const int* __restrict__ rel, int n) {
    int beg = blockIdx.x * (256 * 4) + threadIdx.x;
    int s[4], d[4], r[4];
    bool ok[4];
#pragma unroll
    for (int j = 0; j < 4; j++) {
        int i = beg + j * 256;           // coalesced
        ok[j] = (i < n);
        if (ok[j]) { s[j] = src[i]; d[j] = dst[i]; r[j] = rel[i]; }
    }
    int ks[4], kd[4], os[4], od[4];
#pragma unroll
    for (int j = 0; j < 4; j++) {        // 8 independent atomics back-to-back
        if (ok[j]) {
            ks[j] = (int)(((u32)s[j] >> 14) * NRELS + (u32)r[j]);
            kd[j] = (int)(((u32)d[j] >> 14) * NRELS + (u32)r[j]);
            os[j] = atomicAdd(&g_bincnt[ks[j]], 1);
            od[j] = atomicAdd(&g_bincnt[kd[j]], 1);
        }
    }
#pragma unroll
    for (int j = 0; j < 4; j++) {
        if (ok[j]) {
            if (os[j] < SLAB_CAP) g_slab[(size_t)ks[j] * SLAB_CAP + os[j]] = (u32)s[j];
            if (od[j] < SLAB_CAP) g_slab[(size_t)kd[j] * SLAB_CAP + od[j]] = (u32)d[j] | (1u << 18);
        }
    }
}

// ------- phase 2: one block per bin; accumulate, combine, plain store -------
__global__ void __launch_bounds__(256) reduce_kernel(const float* __restrict__ emb) {
    int key    = blockIdx.x;            // 0..NKEYS-1
    int bucket = key >> 8;              // key / NRELS
    int rel    = key & 255;
    int cnt    = min(g_bincnt[key], SLAB_CAP);

    int t = threadIdx.x;
    int sub = t >> 6;                   // 4 item streams
    int l   = t & 63;
    int q   = l << 2;                   // float4 column

    const u32* bin = g_slab + (size_t)key * SLAB_CAP;

    float4 as = make_float4(0.f, 0.f, 0.f, 0.f);
    float4 ad = as;

    int i = sub;
    // 2 items in flight per stream (8 gathers per 256-thread block iteration)
    for (; i + 4 < cnt; i += 8) {
        u32 p0 = bin[i];                // uniform per stream (broadcast load)
        u32 p1 = bin[i + 4];
        float4 v0 = __ldg((const float4*)&emb[(p0 & 0x3FFFF) * DIM + q]);
        float4 v1 = __ldg((const float4*)&emb[(p1 & 0x3FFFF) * DIM + q]);
        if (p0 >> 18) { ad.x += v0.x; ad.y += v0.y; ad.z += v0.z; ad.w += v0.w; }
        else          { as.x += v0.x; as.y += v0.y; as.z += v0.z; as.w += v0.w; }
        if (p1 >> 18) { ad.x += v1.x; ad.y += v1.y; ad.z += v1.z; ad.w += v1.w; }
        else          { as.x += v1.x; as.y += v1.y; as.z += v1.z; as.w += v1.w; }
    }
    for (; i < cnt; i += 4) {
        u32 p = bin[i];
        float4 v = __ldg((const float4*)&emb[(p & 0x3FFFF) * DIM + q]);
        if (p >> 18) { ad.x += v.x; ad.y += v.y; ad.z += v.z; ad.w += v.w; }
        else         { as.x += v.x; as.y += v.y; as.z += v.z; as.w += v.w; }
    }

    // combine 4 streams in smem, then exclusive-owner plain store
    __shared__ float4 s_s[4][64];
    __shared__ float4 s_d[4][64];
    s_s[sub][l] = as;
    s_d[sub][l] = ad;
    __syncthreads();
    if (sub == 0) {
        float4 a = s_s[0][l], b = s_s[1][l], c = s_s[2][l], e = s_s[3][l];
        a.x += b.x + c.x + e.x; a.y += b.y + c.y + e.y;
        a.z += b.z + c.z + e.z; a.w += b.w + c.w + e.w;
        float4 f = s_d[0][l], g = s_d[1][l], h = s_d[2][l], k = s_d[3][l];
        f.x += g.x + h.x + k.x; f.y += g.y + h.y + k.y;
        f.z += g.z + h.z + k.z; f.w += g.w + h.w + k.w;
        *(float4*)&g_AsumB[bucket][rel * DIM + q]           = a;
        *(float4*)&g_AsumB[bucket][(NRELS + rel) * DIM + q] = f;
    }
}

// ------- phase 3: sum buckets, divide, unpack h, restore bincnt=0 -------
// grid 256 (one block per rel), 128 threads (one float4 output per thread).
__global__ void __launch_bounds__(128) finalize_kernel(const float* __restrict__ dyn) {
    int r = blockIdx.x, t = threadIdx.x;
    int half = t >> 6;           // 0 = src row, 1 = dst row
    int c4   = (t & 63) << 2;    // float column

    float4 acc = make_float4(0.f, 0.f, 0.f, 0.f);
    int items = 0;
#pragma unroll
    for (int b = 0; b < NBUCKETS; b++) {
        items += g_bincnt[(b << 8) + r];
        float4 v = *(const float4*)&g_AsumB[b][(half * NRELS + r) * DIM + c4];
        acc.x += v.x; acc.y += v.y; acc.z += v.z; acc.w += v.w;
    }
    __syncthreads();             // all reads of g_bincnt done before restore
    if (t < NBUCKETS) g_bincnt[(t << 8) + r] = 0;   // invariant for next replay

    int cnt = items >> 1;        // (src+dst items) / 2 = edges for this rel
    float inv = 1.f / (float)(cnt > 0 ? cnt : 1);
    acc.x *= inv; acc.y *= inv; acc.z *= inv; acc.w *= inv;
    *(float4*)&g_A[(half * NRELS + r) * DIM + c4] = acc;

    // unpack dyn [r][0][d][k] (k innermost): float4 at r*512 + 4t covers
    // (d=2t,k=0),(d=2t,k=1),(d=2t+1,k=0),(d=2t+1,k=1)
    float4 dv = *(const float4*)&dyn[r * 512 + t * 4];
    g_A[(512 + r) * DIM + 2 * t]     = dv.x;   // h_src d=2t
    g_A[(768 + r) * DIM + 2 * t]     = dv.y;   // h_dst d=2t
    g_A[(512 + r) * DIM + 2 * t + 1] = dv.z;   // h_src d=2t+1
    g_A[(768 + r) * DIM + 2 * t + 1] = dv.w;   // h_dst d=2t+1
}

// ---- phase 4: GEMM  G[1024][768] = A[1024][256] @ Wsel[768][256]^T ----
// Tile 64(M) x 32(N) x 16(K); grid (24, 16) = 384 blocks.
#define TM 64
#define TN 32
#define TK 16
__global__ void __launch_bounds__(256) gemm_kernel(const float* __restrict__ Wih,
                                                   const float* __restrict__ Whh) {
    __shared__ float As[TK][TM + 4];
    __shared__ float Bs[TK][TN + 4];
    int bm = blockIdx.y, bn = blockIdx.x;
    const float* Wsel = (bm < 8) ? Wih : Whh;

    int tid = threadIdx.x;
    int tx = tid & 15;        // 16 n-subtiles x 2 cols = 32
    int ty = tid >> 4;        // 16 m-subtiles x 4 rows = 64
    int lrow  = tid >> 2;     // 0..63
    int lcol4 = (tid & 3) * 4;

    const float* Aptr = g_A + (bm * TM + lrow) * 256 + lcol4;

    float c[4][2] = {};

    for (int k0 = 0; k0 < 256; k0 += TK) {
        // A tile: 64 rows x 16 cols = 256 float4 -> all 256 threads
        float4 a4 = *(const float4*)(Aptr + k0);
        As[lcol4 + 0][lrow] = a4.x;
        As[lcol4 + 1][lrow] = a4.y;
        As[lcol4 + 2][lrow] = a4.z;
        As[lcol4 + 3][lrow] = a4.w;
        // B tile: 32 rows x 16 cols = 128 float4 -> threads with lrow < 32
        if (lrow < 32) {
            float4 b4 = *(const float4*)(Wsel + (bn * TN + lrow) * 256 + k0 + lcol4);
            Bs[lcol4 + 0][lrow] = b4.x;
            Bs[lcol4 + 1][lrow] = b4.y;
            Bs[lcol4 + 2][lrow] = b4.z;
            Bs[lcol4 + 3][lrow] = b4.w;
        }
        __syncthreads();
#pragma unroll
        for (int kk = 0; kk < TK; kk++) {
            float4 av = *(const float4*)&As[kk][ty * 4];
            float2 bv = *(const float2*)&Bs[kk][tx * 2];
            c[0][0] += av.x * bv.x; c[0][1] += av.x * bv.y;
            c[1][0] += av.y * bv.x; c[1][1] += av.y * bv.y;
            c[2][0] += av.z * bv.x; c[2][1] += av.z * bv.y;
            c[3][0] += av.w * bv.x; c[3][1] += av.w * bv.y;
        }
        __syncthreads();
    }

#pragma unroll
    for (int i = 0; i < 4; i++) {
        int row = bm * TM + ty * 4 + i;
        int col = bn * TN + tx * 2;
        *(float2*)&g_G[row * 768 + col] = make_float2(c[i][0], c[i][1]);
    }
}

// ---------------- phase 5: GRU gates + output ----------------
__global__ void gate_kernel(const float* __restrict__ bih,
                            const float* __restrict__ bhh,
                            float* __restrict__ out) {
    int r = blockIdx.x;
    int d = threadIdx.x;

    float bir = bih[d], biz = bih[256 + d], bin_ = bih[512 + d];
    float bhr = bhh[d], bhz = bhh[256 + d], bhn = bhh[512 + d];

#pragma unroll
    for (int k = 0; k < 2; k++) {   // 0 = src, 1 = dst
        int xrow = k * 256 + r;
        int hrow = 512 + k * 256 + r;
        float ir  = g_G[xrow * 768 + d]       + bir;
        float iz  = g_G[xrow * 768 + 256 + d] + biz;
        float in_ = g_G[xrow * 768 + 512 + d] + bin_;
        float hr  = g_G[hrow * 768 + d]       + bhr;
        float hz  = g_G[hrow * 768 + 256 + d] + bhz;
        float hn  = g_G[hrow * 768 + 512 + d] + bhn;
        float h   = g_A[hrow * DIM + d];

        float rg = 1.f / (1.f + expf(-(ir + hr)));
        float z  = 1.f / (1.f + expf(-(iz + hz)));
        float nv = tanhf(in_ + rg * hn);
        out[r * (DIM * 2) + d * 2 + k] = (1.f - z) * nv + z * h;
    }
}

extern "C" void kernel_launch(void* const* d_in, const int* in_sizes, int n_in,
                              void* d_out, int out_size) {
    const int*   src = (const int*)d_in[0];
    const int*   dst = (const int*)d_in[1];
    const int*   rel = (const int*)d_in[2];
    const float* emb = (const float*)d_in[3];
    const float* dyn = (const float*)d_in[4];
    const float* Wih = (const float*)d_in[5];
    const float* Whh = (const float*)d_in[6];
    const float* bih = (const float*)d_in[7];
    const float* bhh = (const float*)d_in[8];
    float* out = (float*)d_out;
    int n = in_sizes[0];

    int nbS = (n + 1024 - 1) / 1024;
    scatter_kernel<<<nbS, 256>>>(src, dst, rel, n);
    reduce_kernel<<<NKEYS, 256>>>(emb);
    finalize_kernel<<<256, 128>>>(dyn);
    gemm_kernel<<<dim3(24, 16), 256>>>(Wih, Whh);
    gate_kernel<<<256, 256>>>(bih, bhh, out);
}

// round 15
// speedup vs baseline: 1.2866x; 1.0002x over previous
#include <cuda_runtime.h>

#define NE_MAX 500000
#define NRELS 256
#define DIM 256
#define NBUCKETS 13            // node >> 14 for N_NODES=200000
#define NKEYS (NBUCKETS * NRELS)   // 3328 bins
#define SLAB_CAP 2048          // items per bin (avg ~300; huge safety margin)

typedef unsigned int u32;

// ---- scratch (device globals; zero at module load) ----
// Invariant: g_bincnt == 0 at entry of every kernel_launch call.
// finalize_kernel restores it after consuming the counts.
__device__ int   g_bincnt[NKEYS];                   // items per (bucket,rel)
__device__ u32   g_slab[NKEYS * SLAB_CAP];          // node(18) | which(1)<<18
__device__ float g_AsumB[NBUCKETS][2 * NRELS * DIM]; // per-bucket partial sums (6.8MB)
// A: rows 0-255 src_avg, 256-511 dst_avg, 512-767 h_src, 768-1023 h_dst
__device__ float g_A[1024 * DIM];
// G: [1024][768] = A @ Wsel^T  (rows <512 use W_ih, rows >=512 use W_hh)
__device__ float g_G[1024 * 768];

// ------- phase 1: scatter items into per-bin slabs (bump allocation) -------
// 4 edges per thread -> 8 independent atomic+store chains in flight.
__global__ void __launch_bounds__(256) scatter_kernel(const int* __restrict__ src,
                                                      const int* __restrict__ dst,
                                                      const int* __restrict__ rel, int n) {
    int beg = blockIdx.x * (256 * 4) + threadIdx.x;
    int s[4], d[4], r[4];
    bool ok[4];
#pragma unroll
    for (int j = 0; j < 4; j++) {
        int i = beg + j * 256;           // coalesced
        ok[j] = (i < n);
        if (ok[j]) { s[j] = src[i]; d[j] = dst[i]; r[j] = rel[i]; }
    }
    int ks[4], kd[4], os[4], od[4];
#pragma unroll
    for (int j = 0; j < 4; j++) {        // 8 independent atomics back-to-back
        if (ok[j]) {
            ks[j] = (int)(((u32)s[j] >> 14) * NRELS + (u32)r[j]);
            kd[j] = (int)(((u32)d[j] >> 14) * NRELS + (u32)r[j]);
            os[j] = atomicAdd(&g_bincnt[ks[j]], 1);
            od[j] = atomicAdd(&g_bincnt[kd[j]], 1);
        }
    }
#pragma unroll
    for (int j = 0; j < 4; j++) {
        if (ok[j]) {
            if (os[j] < SLAB_CAP) g_slab[(size_t)ks[j] * SLAB_CAP + os[j]] = (u32)s[j];
            if (od[j] < SLAB_CAP) g_slab[(size_t)kd[j] * SLAB_CAP + od[j]] = (u32)d[j] | (1u << 18);
        }
    }
}

// ------- phase 2: one block per bin; accumulate, combine, plain store -------
__global__ void __launch_bounds__(256) reduce_kernel(const float* __restrict__ emb) {
    int key    = blockIdx.x;            // 0..NKEYS-1
    int bucket = key >> 8;              // key / NRELS
    int rel    = key & 255;
    int cnt    = min(g_bincnt[key], SLAB_CAP);

    int t = threadIdx.x;
    int sub = t >> 6;                   // 4 item streams
    int l   = t & 63;
    int q   = l << 2;                   // float4 column

    const u32* bin = g_slab + (size_t)key * SLAB_CAP;

    float4 as = make_float4(0.f, 0.f, 0.f, 0.f);
    float4 ad = as;

    int i = sub;
    // 2 items in flight per stream (8 gathers per 256-thread block iteration)
    for (; i + 4 < cnt; i += 8) {
        u32 p0 = bin[i];                // uniform per stream (broadcast load)
        u32 p1 = bin[i + 4];
        float4 v0 = __ldg((const float4*)&emb[(p0 & 0x3FFFF) * DIM + q]);
        float4 v1 = __ldg((const float4*)&emb[(p1 & 0x3FFFF) * DIM + q]);
        if (p0 >> 18) { ad.x += v0.x; ad.y += v0.y; ad.z += v0.z; ad.w += v0.w; }
        else          { as.x += v0.x; as.y += v0.y; as.z += v0.z; as.w += v0.w; }
        if (p1 >> 18) { ad.x += v1.x; ad.y += v1.y; ad.z += v1.z; ad.w += v1.w; }
        else          { as.x += v1.x; as.y += v1.y; as.z += v1.z; as.w += v1.w; }
    }
    for (; i < cnt; i += 4) {
        u32 p = bin[i];
        float4 v = __ldg((const float4*)&emb[(p & 0x3FFFF) * DIM + q]);
        if (p >> 18) { ad.x += v.x; ad.y += v.y; ad.z += v.z; ad.w += v.w; }
        else         { as.x += v.x; as.y += v.y; as.z += v.z; as.w += v.w; }
    }

    // combine 4 streams in smem, then exclusive-owner plain store
    __shared__ float4 s_s[4][64];
    __shared__ float4 s_d[4][64];
    s_s[sub][l] = as;
    s_d[sub][l] = ad;
    __syncthreads();
    if (sub == 0) {
        float4 a = s_s[0][l], b = s_s[1][l], c = s_s[2][l], e = s_s[3][l];
        a.x += b.x + c.x + e.x; a.y += b.y + c.y + e.y;
        a.z += b.z + c.z + e.z; a.w += b.w + c.w + e.w;
        float4 f = s_d[0][l], g = s_d[1][l], h = s_d[2][l], k = s_d[3][l];
        f.x += g.x + h.x + k.x; f.y += g.y + h.y + k.y;
        f.z += g.z + h.z + k.z; f.w += g.w + h.w + k.w;
        *(float4*)&g_AsumB[bucket][rel * DIM + q]           = a;
        *(float4*)&g_AsumB[bucket][(NRELS + rel) * DIM + q] = f;
    }
}

// ------- phase 3: sum buckets, divide, unpack h, restore bincnt=0 -------
// grid 256 (one block per rel), 128 threads (one float4 output per thread).
__global__ void __launch_bounds__(128) finalize_kernel(const float* __restrict__ dyn) {
    int r = blockIdx.x, t = threadIdx.x;
    int half = t >> 6;           // 0 = src row, 1 = dst row
    int c4   = (t & 63) << 2;    // float column

    float4 acc = make_float4(0.f, 0.f, 0.f, 0.f);
    int items = 0;
#pragma unroll
    for (int b = 0; b < NBUCKETS; b++) {
        items += g_bincnt[(b << 8) + r];
        float4 v = *(const float4*)&g_AsumB[b][(half * NRELS + r) * DIM + c4];
        acc.x += v.x; acc.y += v.y; acc.z += v.z; acc.w += v.w;
    }
    __syncthreads();             // all reads of g_bincnt done before restore
    if (t < NBUCKETS) g_bincnt[(t << 8) + r] = 0;   // invariant for next replay

    int cnt = items >> 1;        // (src+dst items) / 2 = edges for this rel
    float inv = 1.f / (float)(cnt > 0 ? cnt : 1);
    acc.x *= inv; acc.y *= inv; acc.z *= inv; acc.w *= inv;
    *(float4*)&g_A[(half * NRELS + r) * DIM + c4] = acc;

    // unpack dyn [r][0][d][k] (k innermost): float4 at r*512 + 4t covers
    // (d=2t,k=0),(d=2t,k=1),(d=2t+1,k=0),(d=2t+1,k=1)
    float4 dv = *(const float4*)&dyn[r * 512 + t * 4];
    g_A[(512 + r) * DIM + 2 * t]     = dv.x;   // h_src d=2t
    g_A[(768 + r) * DIM + 2 * t]     = dv.y;   // h_dst d=2t
    g_A[(512 + r) * DIM + 2 * t + 1] = dv.z;   // h_src d=2t+1
    g_A[(768 + r) * DIM + 2 * t + 1] = dv.w;   // h_dst d=2t+1
}

// ---- phase 4: GEMM  G[1024][768] = A[1024][256] @ Wsel[768][256]^T ----
// Tile 64(M) x 64(N) x 16(K); grid (12, 16) = 192 blocks. (R13 measured-best)
#define TM 64
#define TN 64
#define TK 16
__global__ void __launch_bounds__(256) gemm_kernel(const float* __restrict__ Wih,
                                                   const float* __restrict__ Whh) {
    __shared__ float As[TK][TM + 4];
    __shared__ float Bs[TK][TN + 4];
    int bm = blockIdx.y, bn = blockIdx.x;
    const float* Wsel = (bm < 8) ? Wih : Whh;

    int tid = threadIdx.x;
    int tx = tid & 15;
    int ty = tid >> 4;
    int lrow  = tid >> 2;
    int lcol4 = (tid & 3) * 4;

    const float* Aptr = g_A  + (bm * TM + lrow) * 256 + lcol4;
    const float* Bptr = Wsel + (bn * TN + lrow) * 256 + lcol4;

    float c[4][4] = {};

    for (int k0 = 0; k0 < 256; k0 += TK) {
        float4 a4 = *(const float4*)(Aptr + k0);
        float4 b4 = *(const float4*)(Bptr + k0);
        As[lcol4 + 0][lrow] = a4.x;
        As[lcol4 + 1][lrow] = a4.y;
        As[lcol4 + 2][lrow] = a4.z;
        As[lcol4 + 3][lrow] = a4.w;
        Bs[lcol4 + 0][lrow] = b4.x;
        Bs[lcol4 + 1][lrow] = b4.y;
        Bs[lcol4 + 2][lrow] = b4.z;
        Bs[lcol4 + 3][lrow] = b4.w;
        __syncthreads();
#pragma unroll
        for (int kk = 0; kk < TK; kk++) {
            float4 av = *(const float4*)&As[kk][ty * 4];
            float4 bv = *(const float4*)&Bs[kk][tx * 4];
            c[0][0] += av.x * bv.x; c[0][1] += av.x * bv.y; c[0][2] += av.x * bv.z; c[0][3] += av.x * bv.w;
            c[1][0] += av.y * bv.x; c[1][1] += av.y * bv.y; c[1][2] += av.y * bv.z; c[1][3] += av.y * bv.w;
            c[2][0] += av.z * bv.x; c[2][1] += av.z * bv.y; c[2][2] += av.z * bv.z; c[2][3] += av.z * bv.w;
            c[3][0] += av.w * bv.x; c[3][1] += av.w * bv.y; c[3][2] += av.w * bv.z; c[3][3] += av.w * bv.w;
        }
        __syncthreads();
    }

#pragma unroll
    for (int i = 0; i < 4; i++) {
        int row = bm * TM + ty * 4 + i;
        int col = bn * TN + tx * 4;
        float4 v = make_float4(c[i][0], c[i][1], c[i][2], c[i][3]);
        *(float4*)&g_G[row * 768 + col] = v;
    }
}

// ---------------- phase 5: GRU gates + output ----------------
__global__ void gate_kernel(const float* __restrict__ bih,
                            const float* __restrict__ bhh,
                            float* __restrict__ out) {
    int r = blockIdx.x;
    int d = threadIdx.x;

    float bir = bih[d], biz = bih[256 + d], bin_ = bih[512 + d];
    float bhr = bhh[d], bhz = bhh[256 + d], bhn = bhh[512 + d];

#pragma unroll
    for (int k = 0; k < 2; k++) {   // 0 = src, 1 = dst
        int xrow = k * 256 + r;
        int hrow = 512 + k * 256 + r;
        float ir  = g_G[xrow * 768 + d]       + bir;
        float iz  = g_G[xrow * 768 + 256 + d] + biz;
        float in_ = g_G[xrow * 768 + 512 + d] + bin_;
        float hr  = g_G[hrow * 768 + d]       + bhr;
        float hz  = g_G[hrow * 768 + 256 + d] + bhz;
        float hn  = g_G[hrow * 768 + 512 + d] + bhn;
        float h   = g_A[hrow * DIM + d];

        float rg = 1.f / (1.f + expf(-(ir + hr)));
        float z  = 1.f / (1.f + expf(-(iz + hz)));
        float nv = tanhf(in_ + rg * hn);
        out[r * (DIM * 2) + d * 2 + k] = (1.f - z) * nv + z * h;
    }
}

extern "C" void kernel_launch(void* const* d_in, const int* in_sizes, int n_in,
                              void* d_out, int out_size) {
    const int*   src = (const int*)d_in[0];
    const int*   dst = (const int*)d_in[1];
    const int*   rel = (const int*)d_in[2];
    const float* emb = (const float*)d_in[3];
    const float* dyn = (const float*)d_in[4];
    const float* Wih = (const float*)d_in[5];
    const float* Whh = (const float*)d_in[6];
    const float* bih = (const float*)d_in[7];
    const float* bhh = (const float*)d_in[8];
    float* out = (float*)d_out;
    int n = in_sizes[0];

    int nbS = (n + 1024 - 1) / 1024;
    scatter_kernel<<<nbS, 256>>>(src, dst, rel, n);
    reduce_kernel<<<NKEYS, 256>>>(emb);
    finalize_kernel<<<256, 128>>>(dyn);
    gemm_kernel<<<dim3(12, 16), 256>>>(Wih, Whh);
    gate_kernel<<<256, 256>>>(bih, bhh, out);
}

// round 16
// speedup vs baseline: 1.3482x; 1.0479x over previous
#include <cuda_runtime.h>

#define NE_MAX 500000
#define NRELS 256
#define DIM 256
#define NBUCKETS 13            // node >> 14 for N_NODES=200000
#define NKEYS (NBUCKETS * NRELS)   // 3328 bins
#define SLAB_CAP 2048          // items per bin (avg ~300; huge safety margin)

typedef unsigned int u32;

// ---- scratch (device globals; zero at module load) ----
// Invariant: g_bincnt == 0 at entry of every kernel_launch call.
// finalize_kernel restores it after consuming the counts.
__device__ int   g_bincnt[NKEYS];                   // items per (bucket,rel)
__device__ u32   g_slab[NKEYS * SLAB_CAP];          // node(18) | which(1)<<18
__device__ float g_AsumB[NBUCKETS][2 * NRELS * DIM]; // per-bucket partial sums (6.8MB)
// A: rows 0-255 src_avg, 256-511 dst_avg, 512-767 h_src, 768-1023 h_dst
__device__ float g_A[1024 * DIM];
// G partials: [ksplit][1024][768]; rows <512 use W_ih, rows >=512 use W_hh
__device__ float g_Gp[2][1024 * 768];

// ------- phase 1: scatter items into per-bin slabs (bump allocation) -------
// 4 edges per thread -> 8 independent atomic+store chains in flight.
__global__ void __launch_bounds__(256) scatter_kernel(const int* __restrict__ src,
                                                      const int* __restrict__ dst,
                                                      const int* __restrict__ rel, int n) {
    int beg = blockIdx.x * (256 * 4) + threadIdx.x;
    int s[4], d[4], r[4];
    bool ok[4];
#pragma unroll
    for (int j = 0; j < 4; j++) {
        int i = beg + j * 256;           // coalesced
        ok[j] = (i < n);
        if (ok[j]) { s[j] = src[i]; d[j] = dst[i]; r[j] = rel[i]; }
    }
    int ks[4], kd[4], os[4], od[4];
#pragma unroll
    for (int j = 0; j < 4; j++) {        // 8 independent atomics back-to-back
        if (ok[j]) {
            ks[j] = (int)(((u32)s[j] >> 14) * NRELS + (u32)r[j]);
            kd[j] = (int)(((u32)d[j] >> 14) * NRELS + (u32)r[j]);
            os[j] = atomicAdd(&g_bincnt[ks[j]], 1);
            od[j] = atomicAdd(&g_bincnt[kd[j]], 1);
        }
    }
#pragma unroll
    for (int j = 0; j < 4; j++) {
        if (ok[j]) {
            if (os[j] < SLAB_CAP) g_slab[(size_t)ks[j] * SLAB_CAP + os[j]] = (u32)s[j];
            if (od[j] < SLAB_CAP) g_slab[(size_t)kd[j] * SLAB_CAP + od[j]] = (u32)d[j] | (1u << 18);
        }
    }
}

// ------- phase 2: one block per bin; accumulate, combine, plain store -------
__global__ void __launch_bounds__(256) reduce_kernel(const float* __restrict__ emb) {
    int key    = blockIdx.x;            // 0..NKEYS-1
    int bucket = key >> 8;              // key / NRELS
    int rel    = key & 255;
    int cnt    = min(g_bincnt[key], SLAB_CAP);

    int t = threadIdx.x;
    int sub = t >> 6;                   // 4 item streams
    int l   = t & 63;
    int q   = l << 2;                   // float4 column

    const u32* bin = g_slab + (size_t)key * SLAB_CAP;

    float4 as = make_float4(0.f, 0.f, 0.f, 0.f);
    float4 ad = as;

    int i = sub;
    // 2 items in flight per stream (8 gathers per 256-thread block iteration)
    for (; i + 4 < cnt; i += 8) {
        u32 p0 = bin[i];                // uniform per stream (broadcast load)
        u32 p1 = bin[i + 4];
        float4 v0 = __ldg((const float4*)&emb[(p0 & 0x3FFFF) * DIM + q]);
        float4 v1 = __ldg((const float4*)&emb[(p1 & 0x3FFFF) * DIM + q]);
        if (p0 >> 18) { ad.x += v0.x; ad.y += v0.y; ad.z += v0.z; ad.w += v0.w; }
        else          { as.x += v0.x; as.y += v0.y; as.z += v0.z; as.w += v0.w; }
        if (p1 >> 18) { ad.x += v1.x; ad.y += v1.y; ad.z += v1.z; ad.w += v1.w; }
        else          { as.x += v1.x; as.y += v1.y; as.z += v1.z; as.w += v1.w; }
    }
    for (; i < cnt; i += 4) {
        u32 p = bin[i];
        float4 v = __ldg((const float4*)&emb[(p & 0x3FFFF) * DIM + q]);
        if (p >> 18) { ad.x += v.x; ad.y += v.y; ad.z += v.z; ad.w += v.w; }
        else         { as.x += v.x; as.y += v.y; as.z += v.z; as.w += v.w; }
    }

    // combine 4 streams in smem, then exclusive-owner plain store
    __shared__ float4 s_s[4][64];
    __shared__ float4 s_d[4][64];
    s_s[sub][l] = as;
    s_d[sub][l] = ad;
    __syncthreads();
    if (sub == 0) {
        float4 a = s_s[0][l], b = s_s[1][l], c = s_s[2][l], e = s_s[3][l];
        a.x += b.x + c.x + e.x; a.y += b.y + c.y + e.y;
        a.z += b.z + c.z + e.z; a.w += b.w + c.w + e.w;
        float4 f = s_d[0][l], g = s_d[1][l], h = s_d[2][l], k = s_d[3][l];
        f.x += g.x + h.x + k.x; f.y += g.y + h.y + k.y;
        f.z += g.z + h.z + k.z; f.w += g.w + h.w + k.w;
        *(float4*)&g_AsumB[bucket][rel * DIM + q]           = a;
        *(float4*)&g_AsumB[bucket][(NRELS + rel) * DIM + q] = f;
    }
}

// ------- phase 3: sum buckets, divide, unpack h, restore bincnt=0 -------
// grid 256 (one block per rel), 128 threads (one float4 output per thread).
__global__ void __launch_bounds__(128) finalize_kernel(const float* __restrict__ dyn) {
    int r = blockIdx.x, t = threadIdx.x;
    int half = t >> 6;           // 0 = src row, 1 = dst row
    int c4   = (t & 63) << 2;    // float column

    float4 acc = make_float4(0.f, 0.f, 0.f, 0.f);
    int items = 0;
#pragma unroll
    for (int b = 0; b < NBUCKETS; b++) {
        items += g_bincnt[(b << 8) + r];
        float4 v = *(const float4*)&g_AsumB[b][(half * NRELS + r) * DIM + c4];
        acc.x += v.x; acc.y += v.y; acc.z += v.z; acc.w += v.w;
    }
    __syncthreads();             // all reads of g_bincnt done before restore
    if (t < NBUCKETS) g_bincnt[(t << 8) + r] = 0;   // invariant for next replay

    int cnt = items >> 1;        // (src+dst items) / 2 = edges for this rel
    float inv = 1.f / (float)(cnt > 0 ? cnt : 1);
    acc.x *= inv; acc.y *= inv; acc.z *= inv; acc.w *= inv;
    *(float4*)&g_A[(half * NRELS + r) * DIM + c4] = acc;

    // unpack dyn [r][0][d][k] (k innermost): float4 at r*512 + 4t covers
    // (d=2t,k=0),(d=2t,k=1),(d=2t+1,k=0),(d=2t+1,k=1)
    float4 dv = *(const float4*)&dyn[r * 512 + t * 4];
    g_A[(512 + r) * DIM + 2 * t]     = dv.x;   // h_src d=2t
    g_A[(768 + r) * DIM + 2 * t]     = dv.y;   // h_dst d=2t
    g_A[(512 + r) * DIM + 2 * t + 1] = dv.z;   // h_src d=2t+1
    g_A[(768 + r) * DIM + 2 * t + 1] = dv.w;   // h_dst d=2t+1
}

// ---- phase 4: GEMM  Gp[z] = A[:, z*128:(z+1)*128] @ Wsel[:, same]^T ----
// Tile 64(M) x 64(N) x 16(K); K split in 2; grid (12, 16, 2) = 384 blocks.
// Prefetch double-buffer: next k-tile's LDG overlaps current FMA loop.
#define TM 64
#define TN 64
#define TK 16
#define KHALF 128
__global__ void __launch_bounds__(256) gemm_kernel(const float* __restrict__ Wih,
                                                   const float* __restrict__ Whh) {
    __shared__ float As[TK][TM + 4];
    __shared__ float Bs[TK][TN + 4];
    int bm = blockIdx.y, bn = blockIdx.x, bz = blockIdx.z;
    const float* Wsel = (bm < 8) ? Wih : Whh;
    int kbeg = bz * KHALF;

    int tid = threadIdx.x;
    int tx = tid & 15;
    int ty = tid >> 4;
    int lrow  = tid >> 2;
    int lcol4 = (tid & 3) * 4;

    const float* Aptr = g_A  + (bm * TM + lrow) * 256 + lcol4 + kbeg;
    const float* Bptr = Wsel + (bn * TN + lrow) * 256 + lcol4 + kbeg;

    float c[4][4] = {};

    float4 a4 = *(const float4*)(Aptr);
    float4 b4 = *(const float4*)(Bptr);

    for (int k0 = 0; k0 < KHALF; k0 += TK) {
        As[lcol4 + 0][lrow] = a4.x;
        As[lcol4 + 1][lrow] = a4.y;
        As[lcol4 + 2][lrow] = a4.z;
        As[lcol4 + 3][lrow] = a4.w;
        Bs[lcol4 + 0][lrow] = b4.x;
        Bs[lcol4 + 1][lrow] = b4.y;
        Bs[lcol4 + 2][lrow] = b4.z;
        Bs[lcol4 + 3][lrow] = b4.w;
        __syncthreads();

        // prefetch next k-tile while computing this one
        float4 a4n = a4, b4n = b4;
        if (k0 + TK < KHALF) {
            a4n = *(const float4*)(Aptr + k0 + TK);
            b4n = *(const float4*)(Bptr + k0 + TK);
        }

#pragma unroll
        for (int kk = 0; kk < TK; kk++) {
            float4 av = *(const float4*)&As[kk][ty * 4];
            float4 bv = *(const float4*)&Bs[kk][tx * 4];
            c[0][0] += av.x * bv.x; c[0][1] += av.x * bv.y; c[0][2] += av.x * bv.z; c[0][3] += av.x * bv.w;
            c[1][0] += av.y * bv.x; c[1][1] += av.y * bv.y; c[1][2] += av.y * bv.z; c[1][3] += av.y * bv.w;
            c[2][0] += av.z * bv.x; c[2][1] += av.z * bv.y; c[2][2] += av.z * bv.z; c[2][3] += av.z * bv.w;
            c[3][0] += av.w * bv.x; c[3][1] += av.w * bv.y; c[3][2] += av.w * bv.z; c[3][3] += av.w * bv.w;
        }
        __syncthreads();
        a4 = a4n;
        b4 = b4n;
    }

#pragma unroll
    for (int i = 0; i < 4; i++) {
        int row = bm * TM + ty * 4 + i;
        int col = bn * TN + tx * 4;
        float4 v = make_float4(c[i][0], c[i][1], c[i][2], c[i][3]);
        *(float4*)&g_Gp[bz][row * 768 + col] = v;
    }
}

// ---------------- phase 5: GRU gates + output (sums K-split partials) --------
__global__ void gate_kernel(const float* __restrict__ bih,
                            const float* __restrict__ bhh,
                            float* __restrict__ out) {
    int r = blockIdx.x;
    int d = threadIdx.x;

    float bir = bih[d], biz = bih[256 + d], bin_ = bih[512 + d];
    float bhr = bhh[d], bhz = bhh[256 + d], bhn = bhh[512 + d];

#pragma unroll
    for (int k = 0; k < 2; k++) {   // 0 = src, 1 = dst
        int xrow = k * 256 + r;
        int hrow = 512 + k * 256 + r;
        float ir  = g_Gp[0][xrow * 768 + d]       + g_Gp[1][xrow * 768 + d]       + bir;
        float iz  = g_Gp[0][xrow * 768 + 256 + d] + g_Gp[1][xrow * 768 + 256 + d] + biz;
        float in_ = g_Gp[0][xrow * 768 + 512 + d] + g_Gp[1][xrow * 768 + 512 + d] + bin_;
        float hr  = g_Gp[0][hrow * 768 + d]       + g_Gp[1][hrow * 768 + d]       + bhr;
        float hz  = g_Gp[0][hrow * 768 + 256 + d] + g_Gp[1][hrow * 768 + 256 + d] + bhz;
        float hn  = g_Gp[0][hrow * 768 + 512 + d] + g_Gp[1][hrow * 768 + 512 + d] + bhn;
        float h   = g_A[hrow * DIM + d];

        float rg = 1.f / (1.f + expf(-(ir + hr)));
        float z  = 1.f / (1.f + expf(-(iz + hz)));
        float nv = tanhf(in_ + rg * hn);
        out[r * (DIM * 2) + d * 2 + k] = (1.f - z) * nv + z * h;
    }
}

extern "C" void kernel_launch(void* const* d_in, const int* in_sizes, int n_in,
                              void* d_out, int out_size) {
    const int*   src = (const int*)d_in[0];
    const int*   dst = (const int*)d_in[1];
    const int*   rel = (const int*)d_in[2];
    const float* emb = (const float*)d_in[3];
    const float* dyn = (const float*)d_in[4];
    const float* Wih = (const float*)d_in[5];
    const float* Whh = (const float*)d_in[6];
    const float* bih = (const float*)d_in[7];
    const float* bhh = (const float*)d_in[8];
    float* out = (float*)d_out;
    int n = in_sizes[0];

    int nbS = (n + 1024 - 1) / 1024;
    scatter_kernel<<<nbS, 256>>>(src, dst, rel, n);
    reduce_kernel<<<NKEYS, 256>>>(emb);
    finalize_kernel<<<256, 128>>>(dyn);
    gemm_kernel<<<dim3(12, 16, 2), 256>>>(Wih, Whh);
    gate_kernel<<<256, 256>>>(bih, bhh, out);
}